// round 2
// baseline (speedup 1.0000x reference)
#include <cuda_runtime.h>
#include <cuda_bf16.h>

#define HID    256
#define QLEN   64
#define NOPS   9
#define NCOLS  16
#define TSTEPS 4
#define NNUM   8

// ops: SUM=0 COUNT=1 DIFF=2 GREATER=3 LESSER=4 AND=5 OR=6 ASSIGN=7 RESET=8

// ---------------- device-global scratch (no allocations allowed) ----------------
__device__ float  g_px[QLEN * HID];      // Wx @ emb[q[t]]
__device__ float  g_M1[HID * NOPS];      // W_hist[:,0:256]   @ op_emb^T
__device__ float  g_M2[HID * NCOLS];     // W_hist[:,256:512] @ col_emb^T
__device__ float  g_aop[TSTEPS * NOPS];
__device__ float  g_acol[TSTEPS * NCOLS];
__device__ float  g_piv[2];              // [0]=l_pivot, [1]=g_pivot
__device__ double g_acc[8];              // [0]=sum(rowsum) [1..3]=SW0..2 [4..6]=SC0..2

// ============================================================
// Kernel 1: parallel precompute. grid = 64+9+16 = 89 blocks x 256 threads
// ============================================================
__global__ void k_prep(const int* __restrict__ qids, const float* __restrict__ emb,
                       const float* __restrict__ Wx, const float* __restrict__ Whist,
                       const float* __restrict__ opemb, const float* __restrict__ colemb)
{
    __shared__ float xs[HID];
    int b = blockIdx.x, i = threadIdx.x;
    if (b == 0 && i < 8) g_acc[i] = 0.0;

    const float* wrow;
    float* dst;
    if (b < QLEN) {
        xs[i] = emb[(long)qids[b] * HID + i];
        wrow = Wx + i * HID;
        dst  = g_px + b * HID + i;
    } else if (b < QLEN + NOPS) {
        int o = b - QLEN;
        xs[i] = opemb[o * HID + i];
        wrow = Whist + i * 768;
        dst  = g_M1 + i * NOPS + o;
    } else {
        int c = b - QLEN - NOPS;
        xs[i] = colemb[c * HID + i];
        wrow = Whist + i * 768 + 256;
        dst  = g_M2 + i * NCOLS + c;
    }
    __syncthreads();
    const float4* w4 = (const float4*)wrow;
    const float4* x4 = (const float4*)xs;
    float s = 0.f;
#pragma unroll
    for (int q = 0; q < HID / 4; q++) {
        float4 a = w4[q], x = x4[q];
        s += a.x * x.x + a.y * x.y + a.z * x.z + a.w * x.w;
    }
    *dst = s;
}

// ============================================================
// Kernel 2: single-block sequential core (RNN + pivots + selector chain)
// 512 threads: 2 threads per output row; Wh split 88 regs + 40 shared.
// ============================================================
#define K2T  512
#define WREG 88
#define WSH  40

// shared layout (in floats)
#define OFF_WSH   0
#define OFF_HBUF  (WSH * K2T)                 // 2*HID
#define OFF_ZZ    (OFF_HBUF + 2 * HID)        // NNUM*HID
#define OFF_UOP   (OFF_ZZ + NNUM * HID)       // HID
#define OFF_UCOL  (OFF_UOP + HID)
#define OFF_HH    (OFF_UCOL + HID)
#define OFF_V3    (OFF_HH + HID)
#define OFF_TOPO  (OFF_V3 + HID)
#define OFF_TOPC  (OFF_TOPO + HID)
#define OFF_RED   (OFF_TOPC + HID)            // 64
#define OFF_AOPS  (OFF_RED + 64)              // 16
#define OFF_ACOLS (OFF_AOPS + 16)             // 16
#define OFF_SNUM  (OFF_ACOLS + 16)            // 8
#define OFF_SLWI  (OFF_SNUM + 8)              // 8
#define K2_FLOATS (OFF_SLWI + 8)
#define K2_SMEM   (K2_FLOATS * 4)

__global__ void __launch_bounds__(K2T, 1)
k_seq(const int* __restrict__ lwi_g, const int* __restrict__ nums_g,
      const float* __restrict__ Wh, const float* __restrict__ Wop,
      const float* __restrict__ Wcol, const float* __restrict__ Whist,
      const float* __restrict__ opemb, const float* __restrict__ colemb,
      const float* __restrict__ Uv)
{
    extern __shared__ float sm[];
    float* wsh    = sm + OFF_WSH;
    float* hbuf   = sm + OFF_HBUF;
    float* zz     = sm + OFF_ZZ;
    float* uop    = sm + OFF_UOP;
    float* ucol   = sm + OFF_UCOL;
    float* hh     = sm + OFF_HH;
    float* v3     = sm + OFF_V3;
    float* topo   = sm + OFF_TOPO;
    float* topc   = sm + OFF_TOPC;
    float* red    = sm + OFF_RED;
    float* aop_s  = sm + OFF_AOPS;
    float* acol_s = sm + OFF_ACOLS;
    float* snum   = sm + OFF_SNUM;
    int*   slwi   = (int*)(sm + OFF_SLWI);

    int tid  = threadIdx.x;
    int i    = tid >> 1, k = tid & 1;
    int lane = tid & 31, wrp = tid >> 5;

    if (tid < NNUM) { slwi[tid] = lwi_g[tid]; snum[tid] = (float)nums_g[tid]; }
    if (tid < HID)  { hbuf[tid] = 0.f; hbuf[HID + tid] = 0.f; hh[tid] = 0.f; }

    // load Wh row-half: 88 weights in registers + 40 in shared (transposed)
    float w[WREG];
    {
        const float* wr = Wh + i * HID + k * 128;
#pragma unroll
        for (int q = 0; q < WREG / 4; q++) {
            float4 a = ((const float4*)wr)[q];
            w[4*q] = a.x; w[4*q+1] = a.y; w[4*q+2] = a.z; w[4*q+3] = a.w;
        }
#pragma unroll
        for (int j = 0; j < WSH; j++)
            wsh[j * K2T + tid] = wr[WREG + j];
    }
    __syncthreads();

    // ---- question RNN: 64 sequential steps ----
    for (int step = 0; step < QLEN; step++) {
        const float4* hc = (const float4*)(hbuf + (step & 1) * HID + k * 128);
        float s = 0.f;
#pragma unroll
        for (int q = 0; q < 32; q++) {
            float4 h4 = hc[q];
            if (q < WREG / 4) {
                s += w[4*q] * h4.x + w[4*q+1] * h4.y + w[4*q+2] * h4.z + w[4*q+3] * h4.w;
            } else {
                int j0 = 4 * (q - WREG / 4);
                s += wsh[(j0    ) * K2T + tid] * h4.x + wsh[(j0 + 1) * K2T + tid] * h4.y
                   + wsh[(j0 + 2) * K2T + tid] * h4.z + wsh[(j0 + 3) * K2T + tid] * h4.w;
            }
        }
        s += __shfl_xor_sync(0xffffffffu, s, 1);
        if (k == 0) {
            float val = tanhf(s + g_px[step * HID + i]);
            hbuf[((step + 1) & 1) * HID + i] = val;
#pragma unroll
            for (int n = 0; n < NNUM; n++)
                if (slwi[n] == step) zz[n * HID + i] = val;
        }
        __syncthreads();
    }
    const float* qv = hbuf;  // QLEN even -> final h is in buffer 0

    // ---- pivots: 16 warps cover (p,n) dot products ----
    {
        int p = wrp >> 3, n = wrp & 7;
        float s = 0.f;
#pragma unroll
        for (int j = 0; j < HID / 32; j++)
            s += zz[n * HID + j * 32 + lane] * Uv[p * HID + j * 32 + lane];
#pragma unroll
        for (int o = 16; o; o >>= 1) s += __shfl_xor_sync(0xffffffffu, s, o);
        if (lane == 0) red[p * 8 + n] = s;
    }
    __syncthreads();
    if (tid == 0) {
#pragma unroll
        for (int p = 0; p < 2; p++) {
            float m = -1e30f;
            for (int n = 0; n < 8; n++) m = fmaxf(m, red[p * 8 + n]);
            float den = 0.f, num = 0.f;
            for (int n = 0; n < 8; n++) {
                float e = expf(red[p * 8 + n] - m);
                den += e; num += e * snum[n];
            }
            g_piv[p] = num / den;
        }
    }

    // ---- timestep-invariant halves of W_op/W_col applied to q ----
    {
        const float4* q4 = (const float4*)(qv + k * 128);
        const float4* a4 = (const float4*)(Wop  + i * 512 + k * 128);
        const float4* b4 = (const float4*)(Wcol + i * 512 + k * 128);
        float s1 = 0.f, s2 = 0.f;
#pragma unroll
        for (int q = 0; q < 32; q++) {
            float4 h4 = q4[q], a = a4[q], b = b4[q];
            s1 += a.x * h4.x + a.y * h4.y + a.z * h4.z + a.w * h4.w;
            s2 += b.x * h4.x + b.y * h4.y + b.z * h4.z + b.w * h4.w;
        }
        s1 += __shfl_xor_sync(0xffffffffu, s1, 1);
        s2 += __shfl_xor_sync(0xffffffffu, s2, 1);
        if (k == 0) { uop[i] = s1; ucol[i] = s2; }
    }
    __syncthreads();

    // ---- selector chain: 4 timesteps ----
    for (int t = 0; t < TSTEPS; t++) {
        {
            const float4* h4p = (const float4*)(hh + k * 128);
            const float4* a4 = (const float4*)(Wop   + i * 512 + 256 + k * 128);
            const float4* b4 = (const float4*)(Wcol  + i * 512 + 256 + k * 128);
            const float4* c4 = (const float4*)(Whist + i * 768 + 512 + k * 128);
            float s1 = 0.f, s2 = 0.f, s3 = 0.f;
#pragma unroll
            for (int q = 0; q < 32; q++) {
                float4 h4 = h4p[q], a = a4[q], b = b4[q], c = c4[q];
                s1 += a.x * h4.x + a.y * h4.y + a.z * h4.z + a.w * h4.w;
                s2 += b.x * h4.x + b.y * h4.y + b.z * h4.z + b.w * h4.w;
                s3 += c.x * h4.x + c.y * h4.y + c.z * h4.z + c.w * h4.w;
            }
            s1 += __shfl_xor_sync(0xffffffffu, s1, 1);
            s2 += __shfl_xor_sync(0xffffffffu, s2, 1);
            s3 += __shfl_xor_sync(0xffffffffu, s3, 1);
            if (k == 0) {
                topo[i] = tanhf(uop[i] + s1);
                topc[i] = tanhf(ucol[i] + s2);
                v3[i]   = s3;
            }
        }
        __syncthreads();
        // logits
        if (wrp < NOPS) {
            float s = 0.f;
#pragma unroll
            for (int j = 0; j < HID / 32; j++)
                s += opemb[wrp * HID + j * 32 + lane] * topo[j * 32 + lane];
#pragma unroll
            for (int o = 16; o; o >>= 1) s += __shfl_xor_sync(0xffffffffu, s, o);
            if (lane == 0) red[wrp] = s;
        }
        {
            float s = 0.f;
#pragma unroll
            for (int j = 0; j < HID / 32; j++)
                s += colemb[wrp * HID + j * 32 + lane] * topc[j * 32 + lane];
#pragma unroll
            for (int o = 16; o; o >>= 1) s += __shfl_xor_sync(0xffffffffu, s, o);
            if (lane == 0) red[32 + wrp] = s;
        }
        __syncthreads();
        if (tid == 0) {
            float m = -1e30f;
            for (int o = 0; o < NOPS; o++) m = fmaxf(m, red[o]);
            float den = 0.f, e[NOPS];
            for (int o = 0; o < NOPS; o++) { e[o] = expf(red[o] - m); den += e[o]; }
            for (int o = 0; o < NOPS; o++) {
                float a = e[o] / den; aop_s[o] = a; g_aop[t * NOPS + o] = a;
            }
        }
        if (tid == 32) {
            float m = -1e30f;
            for (int c = 0; c < NCOLS; c++) m = fmaxf(m, red[32 + c]);
            float den = 0.f, e[NCOLS];
            for (int c = 0; c < NCOLS; c++) { e[c] = expf(red[32 + c] - m); den += e[c]; }
            for (int c = 0; c < NCOLS; c++) {
                float a = e[c] / den; acol_s[c] = a; g_acol[t * NCOLS + c] = a;
            }
        }
        __syncthreads();
        if (tid < HID) {
            float a = v3[tid];
#pragma unroll
            for (int o = 0; o < NOPS; o++)  a += g_M1[tid * NOPS + o] * aop_s[o];
#pragma unroll
            for (int c = 0; c < NCOLS; c++) a += g_M2[tid * NCOLS + c] * acol_s[c];
            hh[tid] = tanhf(a);
        }
        __syncthreads();
    }
}

// ============================================================
// Kernel 3: fused table pass — sigmoids + 4-step rs chain + lookup + reductions
// ============================================================
#define K3T 256
__global__ void __launch_bounds__(K3T)
k_table(const float* __restrict__ table, float* __restrict__ out, long rows)
{
    __shared__ float sgc[TSTEPS * NCOLS];   // aop[t][GREATER]*acol[t][c]
    __shared__ float slc[TSTEPS * NCOLS];   // aop[t][LESSER] *acol[t][c]
    __shared__ float cAnd[TSTEPS], cOr[TSTEPS], cRst[TSTEPS], cPass[TSTEPS];
    __shared__ float lkv[NCOLS];
    __shared__ float spv[2];
    __shared__ float stage[K3T * 17];       // padded transpose stage
    __shared__ float wred[8 * 7];

    int tid = threadIdx.x;
    if (tid < TSTEPS * NCOLS) {
        int t = tid >> 4, c = tid & 15;
        float ac = g_acol[t * NCOLS + c];
        sgc[tid] = g_aop[t * NOPS + 3] * ac;
        slc[tid] = g_aop[t * NOPS + 4] * ac;
    } else if (tid < 64 + TSTEPS) {
        int t = tid - 64;
        cAnd[t]  = g_aop[t * NOPS + 5];
        cOr[t]   = g_aop[t * NOPS + 6];
        cRst[t]  = g_aop[t * NOPS + 8];
        cPass[t] = g_aop[t * NOPS + 0] + g_aop[t * NOPS + 1]
                 + g_aop[t * NOPS + 2] + g_aop[t * NOPS + 7];
    } else if (tid >= 96 && tid < 96 + NCOLS) {
        lkv[tid - 96] = g_aop[3 * NOPS + 7] * g_acol[3 * NCOLS + (tid - 96)];
    } else if (tid == 112) {
        spv[0] = g_piv[0]; spv[1] = g_piv[1];
    }
    __syncthreads();
    float lp = spv[0], gp = spv[1];

    float accA = 0.f, aW0 = 0.f, aW1 = 0.f, aW2 = 0.f;
    float aC0 = 0.f, aC1 = 0.f, aC2 = 0.f;

    long stride = (long)gridDim.x * K3T;
    for (long base = (long)blockIdx.x * K3T; base < rows; base += stride) {
        long r = base + tid;
        float rs3 = 0.f;
        if (r < rows) {
            const float4* tp = (const float4*)(table + r * NCOLS);
            float4 v0 = tp[0], v1 = tp[1], v2 = tp[2], v3r = tp[3];
            float tv[16] = { v0.x, v0.y, v0.z, v0.w,  v1.x, v1.y, v1.z, v1.w,
                             v2.x, v2.y, v2.z, v2.w,  v3r.x, v3r.y, v3r.z, v3r.w };
            float rowsum = 0.f;
            float dG[4] = {0.f, 0.f, 0.f, 0.f}, dL[4] = {0.f, 0.f, 0.f, 0.f};
#pragma unroll
            for (int c = 0; c < 16; c++) {
                float v = tv[c];
                rowsum += v;
                float sg = __fdividef(1.f, 1.f + __expf(gp - v));  // sigmoid(v - g_pivot)
                float sl = __fdividef(1.f, 1.f + __expf(v - lp));  // sigmoid(l_pivot - v)
#pragma unroll
                for (int t = 0; t < 4; t++) {
                    dG[t] += sg * sgc[t * 16 + c];
                    dL[t] += sl * slc[t * 16 + c];
                }
            }
            accA += rowsum;
            float p1 = 1.f, p2 = 1.f;
#pragma unroll
            for (int t = 0; t < 4; t++) {
                float rs = dG[t] + dL[t] + cAnd[t] * fminf(p1, p2)
                         + cOr[t] * fmaxf(p1, p2) + cRst[t] + cPass[t] * p1;
                if (t == 0) { aW0 += rs * rowsum; aC0 += rs; }
                else if (t == 1) { aW1 += rs * rowsum; aC1 += rs; }
                else if (t == 2) { aW2 += rs * rowsum; aC2 += rs; }
                p2 = p1; p1 = rs;
            }
            rs3 = p1;
        }
        __syncthreads();  // previous stage readers done
#pragma unroll
        for (int c = 0; c < 16; c++) stage[tid * 17 + c] = rs3 * lkv[c];
        __syncthreads();
        long nvals = (rows - base) * 16;
        if (nvals > (long)K3T * 16) nvals = (long)K3T * 16;
#pragma unroll
        for (int m = 0; m < 16; m++) {
            int idx = m * K3T + tid;
            if (idx < nvals) {
                int rr = idx >> 4, cc = idx & 15;
                out[1 + base * 16 + idx] = stage[rr * 17 + cc];
            }
        }
    }

    // block reduction of the 7 accumulators, then one double atomic each
    float vals[7] = { accA, aW0, aW1, aW2, aC0, aC1, aC2 };
#pragma unroll
    for (int kk = 0; kk < 7; kk++) {
        float v = vals[kk];
#pragma unroll
        for (int o = 16; o; o >>= 1) v += __shfl_xor_sync(0xffffffffu, v, o);
        if ((tid & 31) == 0) wred[(tid >> 5) * 7 + kk] = v;
    }
    __syncthreads();
    if (tid < 7) {
        float s = 0.f;
        for (int wi = 0; wi < 8; wi++) s += wred[wi * 7 + tid];
        atomicAdd(&g_acc[tid], (double)s);
    }
}

// ============================================================
// Kernel 4: scalar chain
// ============================================================
__global__ void k_final(float* __restrict__ out, long rows)
{
    double A   = g_acc[0];
    double SW0 = g_acc[1], SW1 = g_acc[2], SW2 = g_acc[3];
    double SC0 = g_acc[4], SC1 = g_acc[5], SC2 = g_acc[6];
    const float* a0 = g_aop;
    const float* a1 = g_aop + NOPS;
    const float* a2 = g_aop + 2 * NOPS;
    const float* a3 = g_aop + 3 * NOPS;
    double s0 = (double)a0[0] * A   + (double)a0[1] * (double)rows;          // DIFF*(0-0)=0
    double s1 = (double)a1[0] * SW0 + (double)a1[1] * SC0 + (double)a1[2] * (0.0 - s0);
    double s2 = (double)a2[0] * SW1 + (double)a2[1] * SC1 + (double)a2[2] * (0.0 - s1);
    double s3 = (double)a3[0] * SW2 + (double)a3[1] * SC2 + (double)a3[2] * (s0 - s2);
    out[0] = (float)s3;
}

// ============================================================
extern "C" void kernel_launch(void* const* d_in, const int* in_sizes, int n_in,
                              void* d_out, int out_size)
{
    const int*   qids   = (const int*)d_in[0];
    const int*   nums   = (const int*)d_in[1];
    const int*   lwi    = (const int*)d_in[2];
    const float* table  = (const float*)d_in[3];
    const float* emb    = (const float*)d_in[4];
    const float* Wx     = (const float*)d_in[5];
    const float* Wh     = (const float*)d_in[6];
    const float* Wop    = (const float*)d_in[7];
    const float* opemb  = (const float*)d_in[8];
    const float* Wcol   = (const float*)d_in[9];
    const float* colemb = (const float*)d_in[10];
    const float* Whist  = (const float*)d_in[11];
    const float* Uv     = (const float*)d_in[12];
    float* out = (float*)d_out;
    long rows = (long)in_sizes[3] / NCOLS;

    cudaFuncSetAttribute(k_seq, cudaFuncAttributeMaxDynamicSharedMemorySize, K2_SMEM);

    k_prep<<<QLEN + NOPS + NCOLS, HID>>>(qids, emb, Wx, Whist, opemb, colemb);
    k_seq<<<1, K2T, K2_SMEM>>>(lwi, nums, Wh, Wop, Wcol, Whist, opemb, colemb, Uv);
    k_table<<<1184, K3T>>>(table, out, rows);
    k_final<<<1, 1>>>(out, rows);
}